// round 1
// baseline (speedup 1.0000x reference)
#include <cuda_runtime.h>

#define N_ROWS 512
#define D_COLS 256
#define EPS 1e-7f
#define NBLK 64
#define ROWS_PER_BLK (N_ROWS / NBLK)   // 8

// Scratch accumulators (zero-initialized at module load; last block resets
// them every call so graph replays stay correct). No device allocation.
__device__ float gS1[D_COLS];
__device__ float gS2[D_COLS];
__device__ float gA[D_COLS];
__device__ float gB[D_COLS];
__device__ float gC[D_COLS];
__device__ unsigned int gCounter;

__global__ void __launch_bounds__(D_COLS)
club_fused_kernel(const float* __restrict__ mu,
                  const float* __restrict__ logvar,
                  const float* __restrict__ h,
                  float* __restrict__ out) {
    const int d  = threadIdx.x;                 // column index 0..255
    const int r0 = blockIdx.x * ROWS_PER_BLK;   // first row for this block

    float s1 = 0.f, s2 = 0.f, a = 0.f, b = 0.f, c = 0.f;

#pragma unroll
    for (int r = 0; r < ROWS_PER_BLK; ++r) {
        const int idx = (r0 + r) * D_COLS + d;  // row-major, coalesced
        const float hv = h[idx];
        const float mv = mu[idx];
        const float lv = logvar[idx];
        const float inv = 1.0f / (expf(lv) + EPS);
        s1 += hv;
        s2 += hv * hv;
        a  += inv * mv;
        b  += inv;
        const float dmh = mv - hv;
        c  += inv * (dmh * dmh - mv * mv);
    }

    // Column-wise cross-block accumulation.
    atomicAdd(&gS1[d], s1);
    atomicAdd(&gS2[d], s2);
    atomicAdd(&gA[d],  a);
    atomicAdd(&gB[d],  b);
    atomicAdd(&gC[d],  c);

    // Last-block-does-combine (threadFenceReduction pattern).
    __threadfence();
    __shared__ bool isLast;
    if (threadIdx.x == 0) {
        unsigned v = atomicAdd(&gCounter, 1u);
        isLast = (v == gridDim.x - 1);
    }
    __syncthreads();
    if (!isLast) return;

    // Coherent reads of the fully-accumulated column stats.
    const float S1 = atomicAdd(&gS1[d], 0.0f);
    const float S2 = atomicAdd(&gS2[d], 0.0f);
    const float A  = atomicAdd(&gA[d],  0.0f);
    const float B  = atomicAdd(&gB[d],  0.0f);
    const float C  = atomicAdd(&gC[d],  0.0f);

    const float invN = 1.0f / (float)N_ROWS;
    float term = C + 2.0f * S1 * invN * A - S2 * invN * B;

    // Reduce 256 column terms -> scalar.
    __shared__ float red[D_COLS];
    red[d] = term;
    __syncthreads();
#pragma unroll
    for (int s = D_COLS / 2; s > 0; s >>= 1) {
        if (d < s) red[d] += red[d + s];
        __syncthreads();
    }

    if (d == 0) {
        out[0]   = -0.5f * invN * red[0];
        gCounter = 0u;            // reset ticket for the next graph replay
    }
    // Reset accumulators for the next call (visible at next kernel launch).
    gS1[d] = 0.f; gS2[d] = 0.f; gA[d] = 0.f; gB[d] = 0.f; gC[d] = 0.f;
}

extern "C" void kernel_launch(void* const* d_in, const int* in_sizes, int n_in,
                              void* d_out, int out_size) {
    const float* mu     = (const float*)d_in[0];
    const float* logvar = (const float*)d_in[1];
    const float* h      = (const float*)d_in[2];
    float* out          = (float*)d_out;
    club_fused_kernel<<<NBLK, D_COLS>>>(mu, logvar, h, out);
}